// round 14
// baseline (speedup 1.0000x reference)
#include <cuda_runtime.h>
#include <cuda_bf16.h>
#include <cstdint>

// Problem constants
#define Bb 2
#define Hh 8
#define NCC 32
#define CC 64
#define OO 2
#define DD 128
#define BH (Bb*Hh)              // 16
#define NTILES (BH*NCC)         // 512
#define TILE_STRIDE (CC*OO*DD)  // 16384
#define OUT_ELEMS (NTILES*TILE_STRIDE) // 8388608
#define NT 512                  // threads per block

// Per-chunk recurrent states: fp32, d-major [tile][d][e]
__device__ float g_state[(size_t)NTILES * DD * DD];   // 33.5 MB

// ---- Consumer SMEM layout (bytes). Row pitch 272 = 17*16B: ldmatrix conflict-free.
#define PB     272
#define A_HI   0
#define A_LO   34816
#define B_HI   69632
#define B_LO   104448
#define D_OFF  139264
#define DPITCH 132                           // floats
#define CONS_SMEM_BYTES (D_OFF + 128*DPITCH*4)   // 206848

// ---- Chain SMEM layout (float offsets). Quarter state: 128 d x 32 e, pitch 33.
#define HP 33
#define SM_HS    0                   // 128*33 = 4224
#define SM_V     4224                // vw0[128] vw1[128] vu0[32] vu1[32] va0[32] va1[32]
#define SM_KTH   (SM_V + 384)        // 2 x 32
#define SM_SWW   (SM_KTH + 64)       // 1 (+pad)
#define SM_NREM  (SM_SWW + 4)        // 2 parity x 128 d x 4 rank (d-major)
#define CHAIN_SMEM_BYTES ((SM_NREM + 1024 + 16) * 4)

static __device__ __forceinline__ uint32_t smem_u32(const void* p) {
    uint32_t a;
    asm("{ .reg .u64 t; cvta.to.shared.u64 t, %1; cvt.u32.u64 %0, t; }" : "=r"(a) : "l"(p));
    return a;
}
static __device__ __forceinline__ void ldsm4(uint32_t* r, uint32_t addr) {
    asm volatile("ldmatrix.sync.aligned.m8n8.x4.shared.b16 {%0,%1,%2,%3}, [%4];"
        : "=r"(r[0]), "=r"(r[1]), "=r"(r[2]), "=r"(r[3]) : "r"(addr));
}
static __device__ __forceinline__ void ldsm4t(uint32_t* r, uint32_t addr) {
    asm volatile("ldmatrix.sync.aligned.m8n8.x4.trans.shared.b16 {%0,%1,%2,%3}, [%4];"
        : "=r"(r[0]), "=r"(r[1]), "=r"(r[2]), "=r"(r[3]) : "r"(addr));
}
static __device__ __forceinline__ void mma16816(float* c, const uint32_t* a,
                                                uint32_t b0, uint32_t b1) {
    asm volatile("mma.sync.aligned.m16n8k16.row.col.f32.bf16.bf16.f32 "
        "{%0,%1,%2,%3}, {%4,%5,%6,%7}, {%8,%9}, {%0,%1,%2,%3};"
        : "+f"(c[0]), "+f"(c[1]), "+f"(c[2]), "+f"(c[3])
        : "r"(a[0]), "r"(a[1]), "r"(a[2]), "r"(a[3]), "r"(b0), "r"(b1));
}
// Rational tanh (fp32)
static __device__ __forceinline__ float tanh_poly(float x) {
    const float p = x * x;
    float num = fmaf(p, -2.76076847742355e-16f, 2.00018790482477e-13f);
    num = fmaf(p, num, -8.60467152213735e-11f);
    num = fmaf(p, num, 5.12229709037114e-08f);
    num = fmaf(p, num, 1.48572235717979e-05f);
    num = fmaf(p, num, 6.37261928875436e-04f);
    num = fmaf(p, num, 4.89352455891786e-03f);
    num *= x;
    float den = fmaf(p, 1.19825839466702e-06f, 1.18534705686654e-04f);
    den = fmaf(p, den, 2.26843463243900e-03f);
    den = fmaf(p, den, 4.89352518554385e-03f);
    return __fdividef(num, den);
}

static __device__ __forceinline__ float load_V(int t, int base, int qt,
    const float* __restrict__ w, const float* __restrict__ u, const float* __restrict__ a) {
    if (t < 256) return w[base + t];                       // vw0 | vw1 (full d)
    const int idx = t - 256, vec = idx >> 5, e = idx & 31;
    const float* src = (vec < 2) ? u : a;
    return src[base + (vec & 1)*DD + qt*32 + e];
}

// ---------------------------------------------------------------------------
// Chain kernel: 64 blocks (16 chains x cluster-4). Each CTA owns 32 e's.
// ---------------------------------------------------------------------------
__global__ __launch_bounds__(NT, 1) __cluster_dims__(4, 1, 1) void chain_kernel(
    const float* __restrict__ q, const float* __restrict__ w,
    const float* __restrict__ u, const float* __restrict__ a,
    const float* __restrict__ init, const int* __restrict__ linflag,
    float* __restrict__ dout)
{
    extern __shared__ float sm[];
    const uint32_t smem_base = smem_u32(sm);
    const int bh = blockIdx.x >> 2, qt = blockIdx.x & 3;
    const int lin = *linflag;

    float* Hs   = sm + SM_HS;
    float* V    = sm + SM_V;
    float* kth  = sm + SM_KTH;
    float* ssww = sm + SM_SWW;
    float* nrem = sm + SM_NREM;
    const int t = threadIdx.x;
    const int l = t & 31, wid = t >> 5;    // wid 0..15

    // Preamble: init quarter state -> Hs AND publish tile 0 (fp32 d-major)
    const float* ip = init + bh * (DD*DD);
    float* st0 = g_state + (size_t)(bh*NCC) * (DD*DD);
    #pragma unroll
    for (int i = 0; i < 8; i++) {
        const int k = t + NT*i;
        const int d = k >> 5, e = k & 31;
        const float v = ip[d*DD + qt*32 + e];
        Hs[d*HP + e] = v;
        st0[d*DD + qt*32 + e] = v;
    }
    {
        const int base0 = ((bh*NCC + 0)*CC + (CC-1))*(OO*DD);
        if (t < 384) V[t] = load_V(t, base0, qt, w, u, a);
    }
    __syncthreads();

    for (int n = 0; n < NCC; n++) {
        const int last = (n == NCC-1);
        const int par = n & 1;

        // ---- prefetch next chunk's V (full-chunk hiding)
        float vpref = 0.f;
        if (!last && t < 384) {
            const int basen = ((bh*NCC + n + 1)*CC + (CC-1))*(OO*DD);
            vpref = load_V(t, basen, qt, w, u, a);
        }

        // ---- kth: warp handles e = wid and wid+16; lanes over d; sww in-warp
        {
            float s0a = 0.f, s1a = 0.f, s0b = 0.f, s1b = 0.f, swp = 0.f;
            #pragma unroll
            for (int i = 0; i < 4; i++) {
                const int d = l + 32*i;
                const float w0 = V[d], w1 = V[128 + d];
                const float ha = Hs[d*HP + wid];
                const float hb = Hs[d*HP + wid + 16];
                s0a = fmaf(w0, ha, s0a);  s1a = fmaf(w1, ha, s1a);
                s0b = fmaf(w0, hb, s0b);  s1b = fmaf(w1, hb, s1b);
                swp = fmaf(w0, w1, swp);
            }
            #pragma unroll
            for (int o = 16; o; o >>= 1) {
                s0a += __shfl_xor_sync(0xffffffffu, s0a, o);
                s1a += __shfl_xor_sync(0xffffffffu, s1a, o);
                s0b += __shfl_xor_sync(0xffffffffu, s0b, o);
                s1b += __shfl_xor_sync(0xffffffffu, s1b, o);
                swp += __shfl_xor_sync(0xffffffffu, swp, o);
            }
            if (l == 0) {
                kth[wid] = s0a;       kth[wid + 16] = s0b;
                kth[32 + wid] = s1a;  kth[32 + wid + 16] = s1b;
                if (wid == 0) *ssww = swp;
            }
        }
        __syncthreads();

        // ---- update + norm (register-resident). lane = e, warp owns 8 d's.
        float hnew[8];
        float ss[8];
        {
            const float sww = *ssww;
            const float uv0 = V[256 + l] - kth[l];
            const float uv1 = V[288 + l] - V[320 + l]*kth[32 + l] - sww*uv0;
            const float cA = V[320 + l] * V[352 + l];
            const float cB = uv0 * V[352 + l];
            const float cC = uv1;
            #pragma unroll
            for (int i = 0; i < 8; i++) {
                const int d = wid + 16*i;
                const float h = Hs[d*HP + l];
                hnew[i] = fmaf(h, cA, fmaf(V[d], cB, V[128 + d]*cC));
                ss[i] = hnew[i] * hnew[i];
            }
            if (!lin) {
                #pragma unroll
                for (int o = 16; o; o >>= 1) {
                    #pragma unroll
                    for (int i = 0; i < 8; i++)
                        ss[i] += __shfl_xor_sync(0xffffffffu, ss[i], o);
                }
                if (l < 8) {
                    const float sj = ss[l];          // sum for d = wid + 16*l
                    const uint32_t myoff = smem_base +
                        (uint32_t)((SM_NREM + par*512 + (wid + 16*l)*4 + qt) * 4);
                    #pragma unroll
                    for (int r = 0; r < 4; r++) {
                        asm volatile(
                            "{ .reg .b32 rr; mapa.shared::cluster.u32 rr, %0, %1; "
                            "st.shared::cluster.f32 [rr], %2; }"
                            :: "r"(myoff), "r"((uint32_t)r), "f"(sj) : "memory");
                    }
                }
            }
        }

        float rnv[8];
        if (!lin) {
            asm volatile("barrier.cluster.arrive.aligned;" ::: "memory");
            asm volatile("barrier.cluster.wait.aligned;" ::: "memory");
            float myrn = 0.f;
            if (l < 8) {
                const float4 nv = *(const float4*)(nrem + par*512 + (wid + 16*l)*4);
                const float s4 = (nv.x + nv.y) + (nv.z + nv.w);
                myrn = __fdividef(2.f, sqrtf(s4) + 1e-6f);
            }
            #pragma unroll
            for (int i = 0; i < 8; i++)
                rnv[i] = __shfl_sync(0xffffffffu, myrn, i);
        }

        // ---- activation (regs) + Hs write + publish
        {
            float* dst = last ? (dout + OUT_ELEMS + bh * (DD*DD))
                              : (g_state + (size_t)(bh*NCC + n + 1) * (DD*DD));
            #pragma unroll
            for (int i = 0; i < 8; i++) {
                const int d = wid + 16*i;
                float val = hnew[i];
                if (!lin) {
                    const float z = val * rnv[i];
                    const float inner = 0.7978845608028654f * fmaf(0.044715f*z*z, z, z);
                    val = 0.25f * val * z * (1.f + tanh_poly(inner));
                }
                Hs[d*HP + l] = val;
                dst[d*DD + qt*32 + l] = val;                 // coalesced 128B/warp
            }
        }
        if (!last && t < 384) V[t] = vpref;
        __syncthreads();
    }
}

// ---------------------------------------------------------------------------
// Consumer kernel: 512 blocks, one tile each. No waiting (kernel ordering).
// 16 warps, warp tile 32m x 32n, bf16 3-term mma.sync -> Dsm, fp32 epilogue.
// ---------------------------------------------------------------------------
__global__ __launch_bounds__(NT, 1) void consume_kernel(
    const float* __restrict__ q, const float* __restrict__ w,
    const float* __restrict__ u, const float* __restrict__ a,
    float* __restrict__ dout)
{
    extern __shared__ float smf[];
    unsigned char* smem_raw = (unsigned char*)smf;
    const uint32_t smem_base = smem_u32(smem_raw);
    const int t = threadIdx.x;
    const int tile = blockIdx.x;
    const int base = tile * TILE_STRIDE;

    // Stage B = H (fp32 d-major) -> bf16 hi/lo smem, rows = d (K-major), pitch PB
    {
        const float4* hp4 = (const float4*)(g_state + (size_t)tile * (DD*DD));
        #pragma unroll
        for (int i = 0; i < 8; i++) {
            const int p = t + NT*i;                // float4 index (4096 total)
            const float4 hv = hp4[p];
            const int d = p >> 5;
            const int ee = (p & 31) * 4;
            const float vs[4] = {hv.x, hv.y, hv.z, hv.w};
            uint32_t hp[2], lp[2];
            #pragma unroll
            for (int jb = 0; jb < 2; jb++) {
                __nv_bfloat16 h0 = __float2bfloat16(vs[jb*2]);
                __nv_bfloat16 h1 = __float2bfloat16(vs[jb*2+1]);
                __nv_bfloat16 l0 = __float2bfloat16(vs[jb*2]   - __bfloat162float(h0));
                __nv_bfloat16 l1 = __float2bfloat16(vs[jb*2+1] - __bfloat162float(h1));
                hp[jb] = (uint32_t)__bfloat16_as_ushort(h0) | ((uint32_t)__bfloat16_as_ushort(h1) << 16);
                lp[jb] = (uint32_t)__bfloat16_as_ushort(l0) | ((uint32_t)__bfloat16_as_ushort(l1) << 16);
            }
            const uint32_t off = (uint32_t)(d*PB + ee*2);
            *(uint32_t*)(smem_raw + B_HI + off)     = hp[0];
            *(uint32_t*)(smem_raw + B_HI + off + 4) = hp[1];
            *(uint32_t*)(smem_raw + B_LO + off)     = lp[0];
            *(uint32_t*)(smem_raw + B_LO + off + 4) = lp[1];
        }
    }

    const int wp = t >> 5, l = t & 31;
    const int lr = l & 7, grp = l >> 3;
    const int mbase = (wp >> 2) * 32;            // 4 m-strips of 32 rows
    const int nbase = (wp & 3) * 32;             // 4 n-groups of 32 cols
    const uint32_t aoffA = (uint32_t)((mbase + lr + ((grp & 1) << 3)) * PB + ((grp >> 1) << 3) * 2);
    const uint32_t boffT = (uint32_t)((lr + ((grp & 1) << 3)) * PB + ((grp >> 1) << 3) * 2);

    #pragma unroll 1
    for (int half = 0; half < 2; half++) {
        // Stage A = X rows (v*32+cc), fp32 -> bf16 hi/lo, rows r, pitch PB
        #pragma unroll
        for (int i = 0; i < 16; i++) {
            const int p = t + NT*i;
            const int r = p >> 6, dp = p & 63;
            const int v = r >> 5, cc = r & 31, c = cc + 32*half;
            const float* src = ((v & 1) ? w : q) + base + c*(OO*DD) + (v >> 1)*DD + dp*2;
            const float2 xv = *(const float2*)src;
            __nv_bfloat16 h0 = __float2bfloat16(xv.x);
            __nv_bfloat16 h1 = __float2bfloat16(xv.y);
            __nv_bfloat16 l0 = __float2bfloat16(xv.x - __bfloat162float(h0));
            __nv_bfloat16 l1 = __float2bfloat16(xv.y - __bfloat162float(h1));
            uint32_t hp = (uint32_t)__bfloat16_as_ushort(h0) | ((uint32_t)__bfloat16_as_ushort(h1) << 16);
            uint32_t lp = (uint32_t)__bfloat16_as_ushort(l0) | ((uint32_t)__bfloat16_as_ushort(l1) << 16);
            const uint32_t off = (uint32_t)(r*PB + dp*4);
            *(uint32_t*)(smem_raw + A_HI + off) = hp;
            *(uint32_t*)(smem_raw + A_LO + off) = lp;
        }
        __syncthreads();

        // GEMM: acc[mtile][nsub][4]
        float acc[2][4][4];
        #pragma unroll
        for (int m = 0; m < 2; m++)
            #pragma unroll
            for (int nn = 0; nn < 4; nn++)
                #pragma unroll
                for (int jj = 0; jj < 4; jj++) acc[m][nn][jj] = 0.f;

        #pragma unroll 1
        for (int k0 = 0; k0 < DD; k0 += 16) {
            uint32_t ah[2][4], al[2][4];
            #pragma unroll
            for (int m = 0; m < 2; m++) {
                ldsm4(ah[m], smem_base + A_HI + aoffA + (uint32_t)(m*16*PB) + k0*2);
                ldsm4(al[m], smem_base + A_LO + aoffA + (uint32_t)(m*16*PB) + k0*2);
            }
            #pragma unroll
            for (int nt = 0; nt < 2; nt++) {
                const uint32_t bo = boffT + (uint32_t)(k0*PB)
                                  + (uint32_t)((nbase + nt*16) * 2);
                uint32_t bhv[4], blv[4];
                ldsm4t(bhv, smem_base + B_HI + bo);
                ldsm4t(blv, smem_base + B_LO + bo);
                #pragma unroll
                for (int m = 0; m < 2; m++) {
                    mma16816(acc[m][nt*2+0], ah[m], bhv[0], bhv[1]);
                    mma16816(acc[m][nt*2+0], ah[m], blv[0], blv[1]);
                    mma16816(acc[m][nt*2+0], al[m], bhv[0], bhv[1]);
                    mma16816(acc[m][nt*2+1], ah[m], bhv[2], bhv[3]);
                    mma16816(acc[m][nt*2+1], ah[m], blv[2], blv[3]);
                    mma16816(acc[m][nt*2+1], al[m], bhv[2], bhv[3]);
                }
            }
        }

        // Fragments -> Dsm
        {
            float* Dsm = (float*)(smem_raw + D_OFF);
            #pragma unroll
            for (int m = 0; m < 2; m++) {
                const int r0 = mbase + m*16 + (l >> 2);
                #pragma unroll
                for (int nn = 0; nn < 4; nn++) {
                    const int ncol = nbase + (nn >> 1)*16 + (nn & 1)*8 + 2*(l & 3);
                    *(float2*)(Dsm + r0*DPITCH + ncol)     = make_float2(acc[m][nn][0], acc[m][nn][1]);
                    *(float2*)(Dsm + (r0+8)*DPITCH + ncol) = make_float2(acc[m][nn][2], acc[m][nn][3]);
                }
            }
        }
        __syncthreads();

        // Epilogue: warp handles 2 c's (cc = wp*2 + it); lane = e/4
        #pragma unroll
        for (int it = 0; it < 2; it++) {
            const int cc = wp*2 + it;
            const int c = cc + 32*half;
            const float* qc = q + base + c*(OO*DD);
            const float* wc = w + base + c*(OO*DD);
            const float* uc = u + base + c*(OO*DD);
            const float* ac = a + base + c*(OO*DD);

            float4 w0l = *(const float4*)(wc + l*4);
            float4 w1l = *(const float4*)(wc + DD + l*4);
            float4 q1l = *(const float4*)(qc + DD + l*4);
            float sw = fmaf(w1l.x, w0l.x, fmaf(w1l.y, w0l.y, fmaf(w1l.z, w0l.z, w1l.w*w0l.w)));
            float sq = fmaf(q1l.x, w0l.x, fmaf(q1l.y, w0l.y, fmaf(q1l.z, w0l.z, q1l.w*w0l.w)));
            #pragma unroll
            for (int o = 16; o; o >>= 1) {
                sw += __shfl_xor_sync(0xffffffffu, sw, o);
                sq += __shfl_xor_sync(0xffffffffu, sq, o);
            }

            const float* Dsm = (const float*)(smem_raw + D_OFF);
            float4 Aq0 = *(const float4*)(Dsm + ( 0 + cc)*DPITCH + 4*l);
            float4 Aw0 = *(const float4*)(Dsm + (32 + cc)*DPITCH + 4*l);
            float4 Aq1 = *(const float4*)(Dsm + (64 + cc)*DPITCH + 4*l);
            float4 Aw1 = *(const float4*)(Dsm + (96 + cc)*DPITCH + 4*l);

            float4 q0e = *(const float4*)(qc + l*4);
            float4 u0e = *(const float4*)(uc + l*4);
            float4 a0e = *(const float4*)(ac + l*4);
            float4 u1e = *(const float4*)(uc + DD + l*4);

            const float aq0[4] = {Aq0.x,Aq0.y,Aq0.z,Aq0.w}, aw0[4] = {Aw0.x,Aw0.y,Aw0.z,Aw0.w};
            const float aq1[4] = {Aq1.x,Aq1.y,Aq1.z,Aq1.w}, aw1[4] = {Aw1.x,Aw1.y,Aw1.z,Aw1.w};
            const float q0s[4] = {q0e.x,q0e.y,q0e.z,q0e.w}, u0s[4] = {u0e.x,u0e.y,u0e.z,u0e.w};
            const float a0s[4] = {a0e.x,a0e.y,a0e.z,a0e.w}, q1s[4] = {q1l.x,q1l.y,q1l.z,q1l.w};
            const float u1s[4] = {u1e.x,u1e.y,u1e.z,u1e.w};
            float o0[4], o1[4];
            #pragma unroll
            for (int e = 0; e < 4; e++) {
                float uv0  = u0s[e] - aw0[e];
                o0[e]      = fmaf(q0s[e], uv0, aq0[e]);
                float kth1 = fmaf(sw, uv0, a0s[e]*aw1[e]);
                float uv1  = u1s[e] - kth1;
                float oi1  = fmaf(sq, uv0, a0s[e]*aq1[e]);
                o1[e]      = fmaf(q1s[e], uv1, oi1);
            }
            *(float4*)(dout + base + c*(OO*DD) + l*4)      = make_float4(o0[0],o0[1],o0[2],o0[3]);
            *(float4*)(dout + base + c*(OO*DD) + DD + l*4) = make_float4(o1[0],o1[1],o1[2],o1[3]);
        }
        __syncthreads();
    }
}

// ---------------------------------------------------------------------------

extern "C" void kernel_launch(void* const* d_in, const int* in_sizes, int n_in,
                              void* d_out, int out_size) {
    const float* q    = (const float*)d_in[0];
    const float* w    = (const float*)d_in[1];
    const float* u    = (const float*)d_in[2];
    const float* a    = (const float*)d_in[3];
    const float* init = (const float*)d_in[4];
    const int*   lin  = (const int*)d_in[5];
    float* out = (float*)d_out;

    cudaFuncSetAttribute(chain_kernel,   cudaFuncAttributeMaxDynamicSharedMemorySize, CHAIN_SMEM_BYTES);
    cudaFuncSetAttribute(consume_kernel, cudaFuncAttributeMaxDynamicSharedMemorySize, CONS_SMEM_BYTES);

    chain_kernel<<<4*BH, NT, CHAIN_SMEM_BYTES>>>(q, w, u, a, init, lin, out);
    consume_kernel<<<NTILES, NT, CONS_SMEM_BYTES>>>(q, w, u, a, out);
}

// round 15
// speedup vs baseline: 1.2319x; 1.2319x over previous
#include <cuda_runtime.h>
#include <cuda_bf16.h>
#include <cstdint>

// Problem constants
#define Bb 2
#define Hh 8
#define NCC 32
#define CC 64
#define OO 2
#define DD 128
#define BH (Bb*Hh)              // 16
#define NTILES (BH*NCC)         // 512
#define TILE_STRIDE (CC*OO*DD)  // 16384
#define OUT_ELEMS (NTILES*TILE_STRIDE) // 8388608
#define GRID 132                // 33 clusters x 4 = one resident wave
#define NCHAINBLK 64            // 16 chains x 4 quarter-CTAs (cluster-4)
#define NT 512                  // threads per block

// Per-chunk recurrent states: fp32, d-major [tile][d][e]
__device__ float g_state[(size_t)NTILES * DD * DD];   // 33.5 MB
__device__ int g_sync[NTILES + 1];  // [0..512) ready counts (4 = ready), [512] ticket

// ---- Consumer SMEM layout (bytes). Row pitch 272 = 17*16B: ldmatrix conflict-free.
#define PB     272
#define A_HI   0
#define A_LO   34816
#define B_HI   69632
#define B_LO   104448
#define D_OFF  139264
#define DPITCH 132                           // floats
#define CTRL_OFF (D_OFF + 128*DPITCH*4)      // 206848
#define SMEM_BYTES (CTRL_OFF + 32)

// ---- Chain SMEM layout (float offsets). Quarter state: 128 d x 32 e, pitch 33.
#define HP 33
#define SM_HS    0                   // 128*33 = 4224
#define SM_V     4224                // vw0[128] vw1[128] vu0[32] vu1[32] va0[32] va1[32]
#define SM_KTH   (SM_V + 384)        // 2 x 32
#define SM_SWW   (SM_KTH + 64)       // 1 (+pad)
#define SM_NREM  (SM_SWW + 4)        // 2 parity x 128 d x 4 rank (d-major)

static __device__ __forceinline__ uint32_t smem_u32(const void* p) {
    uint32_t a;
    asm("{ .reg .u64 t; cvta.to.shared.u64 t, %1; cvt.u32.u64 %0, t; }" : "=r"(a) : "l"(p));
    return a;
}
static __device__ __forceinline__ void ldsm4(uint32_t* r, uint32_t addr) {
    asm volatile("ldmatrix.sync.aligned.m8n8.x4.shared.b16 {%0,%1,%2,%3}, [%4];"
        : "=r"(r[0]), "=r"(r[1]), "=r"(r[2]), "=r"(r[3]) : "r"(addr));
}
static __device__ __forceinline__ void ldsm4t(uint32_t* r, uint32_t addr) {
    asm volatile("ldmatrix.sync.aligned.m8n8.x4.trans.shared.b16 {%0,%1,%2,%3}, [%4];"
        : "=r"(r[0]), "=r"(r[1]), "=r"(r[2]), "=r"(r[3]) : "r"(addr));
}
static __device__ __forceinline__ void mma16816(float* c, const uint32_t* a,
                                                uint32_t b0, uint32_t b1) {
    asm volatile("mma.sync.aligned.m16n8k16.row.col.f32.bf16.bf16.f32 "
        "{%0,%1,%2,%3}, {%4,%5,%6,%7}, {%8,%9}, {%0,%1,%2,%3};"
        : "+f"(c[0]), "+f"(c[1]), "+f"(c[2]), "+f"(c[3])
        : "r"(a[0]), "r"(a[1]), "r"(a[2]), "r"(a[3]), "r"(b0), "r"(b1));
}
static __device__ __forceinline__ void flag_release_add(int* p) {
    asm volatile("red.release.gpu.global.add.s32 [%0], 1;" :: "l"(p) : "memory");
}
static __device__ __forceinline__ int flag_acquire_ld(const int* p) {
    int v;
    asm volatile("ld.acquire.gpu.global.s32 %0, [%1];" : "=r"(v) : "l"(p) : "memory");
    return v;
}
// Rational tanh (fp32)
static __device__ __forceinline__ float tanh_poly(float x) {
    const float p = x * x;
    float num = fmaf(p, -2.76076847742355e-16f, 2.00018790482477e-13f);
    num = fmaf(p, num, -8.60467152213735e-11f);
    num = fmaf(p, num, 5.12229709037114e-08f);
    num = fmaf(p, num, 1.48572235717979e-05f);
    num = fmaf(p, num, 6.37261928875436e-04f);
    num = fmaf(p, num, 4.89352455891786e-03f);
    num *= x;
    float den = fmaf(p, 1.19825839466702e-06f, 1.18534705686654e-04f);
    den = fmaf(p, den, 2.26843463243900e-03f);
    den = fmaf(p, den, 4.89352518554385e-03f);
    return __fdividef(num, den);
}

// ---------------------------------------------------------------------------
// Chain role: cluster-4 per bh. Each CTA owns e in [qt*32, qt*32+32). 512 thr.
// ---------------------------------------------------------------------------
static __device__ __forceinline__ float load_V(int t, int base, int qt,
    const float* __restrict__ w, const float* __restrict__ u, const float* __restrict__ a) {
    if (t < 256) return w[base + t];                       // vw0 | vw1 (full d)
    const int idx = t - 256, vec = idx >> 5, e = idx & 31;
    const float* src = (vec < 2) ? u : a;
    return src[base + (vec & 1)*DD + qt*32 + e];
}

__device__ __forceinline__ void chain_role(
    int bh, int qt, const float* __restrict__ q, const float* __restrict__ w,
    const float* __restrict__ u, const float* __restrict__ a,
    const float* __restrict__ init, int lin, float* __restrict__ dout,
    float* sm, uint32_t smem_base)
{
    float* Hs   = sm + SM_HS;
    float* V    = sm + SM_V;
    float* kth  = sm + SM_KTH;
    float* ssww = sm + SM_SWW;
    float* nrem = sm + SM_NREM;
    const int t = threadIdx.x;
    const int l = t & 31, wid = t >> 5;    // wid 0..15

    // Preamble: init quarter state -> Hs AND publish tile 0 (fp32 d-major)
    const float* ip = init + bh * (DD*DD);
    float* st0 = g_state + (size_t)(bh*NCC) * (DD*DD);
    #pragma unroll
    for (int i = 0; i < 8; i++) {
        const int k = t + NT*i;
        const int d = k >> 5, e = k & 31;
        const float v = ip[d*DD + qt*32 + e];
        Hs[d*HP + e] = v;
        st0[d*DD + qt*32 + e] = v;
    }
    {
        const int base0 = ((bh*NCC + 0)*CC + (CC-1))*(OO*DD);
        if (t < 384) V[t] = load_V(t, base0, qt, w, u, a);
    }
    __syncthreads();
    if (t == 0) flag_release_add(&g_sync[bh*NCC]);

    for (int n = 0; n < NCC; n++) {
        const int last = (n == NCC-1);
        const int par = n & 1;

        // ---- prefetch next chunk's V (full-chunk hiding)
        float vpref = 0.f;
        if (!last && t < 384) {
            const int basen = ((bh*NCC + n + 1)*CC + (CC-1))*(OO*DD);
            vpref = load_V(t, basen, qt, w, u, a);
        }

        // ---- kth: warp handles e = wid and wid+16; lanes over d; sww in-warp
        {
            float s0a = 0.f, s1a = 0.f, s0b = 0.f, s1b = 0.f, swp = 0.f;
            #pragma unroll
            for (int i = 0; i < 4; i++) {
                const int d = l + 32*i;
                const float w0 = V[d], w1 = V[128 + d];
                const float ha = Hs[d*HP + wid];
                const float hb = Hs[d*HP + wid + 16];
                s0a = fmaf(w0, ha, s0a);  s1a = fmaf(w1, ha, s1a);
                s0b = fmaf(w0, hb, s0b);  s1b = fmaf(w1, hb, s1b);
                swp = fmaf(w0, w1, swp);
            }
            #pragma unroll
            for (int o = 16; o; o >>= 1) {
                s0a += __shfl_xor_sync(0xffffffffu, s0a, o);
                s1a += __shfl_xor_sync(0xffffffffu, s1a, o);
                s0b += __shfl_xor_sync(0xffffffffu, s0b, o);
                s1b += __shfl_xor_sync(0xffffffffu, s1b, o);
                swp += __shfl_xor_sync(0xffffffffu, swp, o);
            }
            if (l == 0) {
                kth[wid] = s0a;       kth[wid + 16] = s0b;
                kth[32 + wid] = s1a;  kth[32 + wid + 16] = s1b;
                if (wid == 0) *ssww = swp;
            }
        }
        __syncthreads();

        // ---- update + norm (register-resident). lane = e, warp owns 8 d's.
        float hnew[8];
        float ss[8];
        {
            const float sww = *ssww;
            const float uv0 = V[256 + l] - kth[l];
            const float uv1 = V[288 + l] - V[320 + l]*kth[32 + l] - sww*uv0;
            const float cA = V[320 + l] * V[352 + l];
            const float cB = uv0 * V[352 + l];
            const float cC = uv1;
            #pragma unroll
            for (int i = 0; i < 8; i++) {
                const int d = wid + 16*i;
                const float h = Hs[d*HP + l];
                hnew[i] = fmaf(h, cA, fmaf(V[d], cB, V[128 + d]*cC));
                ss[i] = hnew[i] * hnew[i];
            }
            if (!lin) {
                #pragma unroll
                for (int o = 16; o; o >>= 1) {
                    #pragma unroll
                    for (int i = 0; i < 8; i++)
                        ss[i] += __shfl_xor_sync(0xffffffffu, ss[i], o);
                }
                if (l < 8) {
                    const float sj = ss[l];          // sum for d = wid + 16*l
                    const uint32_t myoff = smem_base +
                        (uint32_t)((SM_NREM + par*512 + (wid + 16*l)*4 + qt) * 4);
                    #pragma unroll
                    for (int r = 0; r < 4; r++) {
                        asm volatile(
                            "{ .reg .b32 rr; mapa.shared::cluster.u32 rr, %0, %1; "
                            "st.shared::cluster.f32 [rr], %2; }"
                            :: "r"(myoff), "r"((uint32_t)r), "f"(sj) : "memory");
                    }
                }
            }
        }

        float rnv[8];
        if (!lin) {
            asm volatile("barrier.cluster.arrive.aligned;" ::: "memory");
            asm volatile("barrier.cluster.wait.aligned;" ::: "memory");
            float myrn = 0.f;
            if (l < 8) {
                const float4 nv = *(const float4*)(nrem + par*512 + (wid + 16*l)*4);
                const float s4 = (nv.x + nv.y) + (nv.z + nv.w);
                myrn = __fdividef(2.f, sqrtf(s4) + 1e-6f);
            }
            #pragma unroll
            for (int i = 0; i < 8; i++)
                rnv[i] = __shfl_sync(0xffffffffu, myrn, i);
        }

        // ---- activation (regs) + Hs write + publish
        {
            float* dst = last ? (dout + OUT_ELEMS + bh * (DD*DD))
                              : (g_state + (size_t)(bh*NCC + n + 1) * (DD*DD));
            #pragma unroll
            for (int i = 0; i < 8; i++) {
                const int d = wid + 16*i;
                float val = hnew[i];
                if (!lin) {
                    const float z = val * rnv[i];
                    const float inner = 0.7978845608028654f * fmaf(0.044715f*z*z, z, z);
                    val = 0.25f * val * z * (1.f + tanh_poly(inner));
                }
                Hs[d*HP + l] = val;
                dst[d*DD + qt*32 + l] = val;                 // coalesced 128B/warp
            }
        }
        if (!last && t < 384) V[t] = vpref;
        __syncthreads();
        if (t == 0 && !last) flag_release_add(&g_sync[bh*NCC + n + 1]);
    }
}

// ---------------------------------------------------------------------------
// Consumer helpers
// ---------------------------------------------------------------------------
static __device__ __forceinline__ void stage_A_half(
    int half, int base, int t,
    const float* __restrict__ q, const float* __restrict__ w,
    unsigned char* smem_raw)
{
    #pragma unroll
    for (int i = 0; i < 16; i++) {
        const int p = t + NT*i;
        const int r = p >> 6, dp = p & 63;
        const int v = r >> 5, cc = r & 31, c = cc + 32*half;
        const float* src = ((v & 1) ? w : q) + base + c*(OO*DD) + (v >> 1)*DD + dp*2;
        const float2 xv = *(const float2*)src;
        __nv_bfloat16 h0 = __float2bfloat16(xv.x);
        __nv_bfloat16 h1 = __float2bfloat16(xv.y);
        __nv_bfloat16 l0 = __float2bfloat16(xv.x - __bfloat162float(h0));
        __nv_bfloat16 l1 = __float2bfloat16(xv.y - __bfloat162float(h1));
        uint32_t hp = (uint32_t)__bfloat16_as_ushort(h0) | ((uint32_t)__bfloat16_as_ushort(h1) << 16);
        uint32_t lp = (uint32_t)__bfloat16_as_ushort(l0) | ((uint32_t)__bfloat16_as_ushort(l1) << 16);
        const uint32_t off = (uint32_t)(r*PB + dp*4);
        *(uint32_t*)(smem_raw + A_HI + off) = hp;
        *(uint32_t*)(smem_raw + A_LO + off) = lp;
    }
}

static __device__ __forceinline__ void stage_B(
    int tile, int t, unsigned char* smem_raw)
{
    const float4* hp4 = (const float4*)(g_state + (size_t)tile * (DD*DD));
    #pragma unroll
    for (int i = 0; i < 8; i++) {
        const int p = t + NT*i;                // float4 index (4096 total)
        const float4 hv = hp4[p];
        const int d = p >> 5;
        const int ee = (p & 31) * 4;
        const float vs[4] = {hv.x, hv.y, hv.z, hv.w};
        uint32_t hp[2], lp[2];
        #pragma unroll
        for (int jb = 0; jb < 2; jb++) {
            __nv_bfloat16 h0 = __float2bfloat16(vs[jb*2]);
            __nv_bfloat16 h1 = __float2bfloat16(vs[jb*2+1]);
            __nv_bfloat16 l0 = __float2bfloat16(vs[jb*2]   - __bfloat162float(h0));
            __nv_bfloat16 l1 = __float2bfloat16(vs[jb*2+1] - __bfloat162float(h1));
            hp[jb] = (uint32_t)__bfloat16_as_ushort(h0) | ((uint32_t)__bfloat16_as_ushort(h1) << 16);
            lp[jb] = (uint32_t)__bfloat16_as_ushort(l0) | ((uint32_t)__bfloat16_as_ushort(l1) << 16);
        }
        const uint32_t off = (uint32_t)(d*PB + ee*2);
        *(uint32_t*)(smem_raw + B_HI + off)     = hp[0];
        *(uint32_t*)(smem_raw + B_HI + off + 4) = hp[1];
        *(uint32_t*)(smem_raw + B_LO + off)     = lp[0];
        *(uint32_t*)(smem_raw + B_LO + off + 4) = lp[1];
    }
}

// GEMM one half + write fragments to Dsm
static __device__ __forceinline__ void gemm_half(
    int wp, int l, uint32_t smem_base, unsigned char* smem_raw)
{
    const int lr = l & 7, grp = l >> 3;
    const int mbase = (wp >> 2) * 32;
    const int nbase = (wp & 3) * 32;
    const uint32_t aoffA = (uint32_t)((mbase + lr + ((grp & 1) << 3)) * PB + ((grp >> 1) << 3) * 2);
    const uint32_t boffT = (uint32_t)((lr + ((grp & 1) << 3)) * PB + ((grp >> 1) << 3) * 2);

    float acc[2][4][4];
    #pragma unroll
    for (int m = 0; m < 2; m++)
        #pragma unroll
        for (int nn = 0; nn < 4; nn++)
            #pragma unroll
            for (int jj = 0; jj < 4; jj++) acc[m][nn][jj] = 0.f;

    #pragma unroll 1
    for (int k0 = 0; k0 < DD; k0 += 16) {
        uint32_t ah[2][4], al[2][4];
        #pragma unroll
        for (int m = 0; m < 2; m++) {
            ldsm4(ah[m], smem_base + A_HI + aoffA + (uint32_t)(m*16*PB) + k0*2);
            ldsm4(al[m], smem_base + A_LO + aoffA + (uint32_t)(m*16*PB) + k0*2);
        }
        #pragma unroll
        for (int nt = 0; nt < 2; nt++) {
            const uint32_t bo = boffT + (uint32_t)(k0*PB)
                              + (uint32_t)((nbase + nt*16) * 2);
            uint32_t bhv[4], blv[4];
            ldsm4t(bhv, smem_base + B_HI + bo);
            ldsm4t(blv, smem_base + B_LO + bo);
            #pragma unroll
            for (int m = 0; m < 2; m++) {
                mma16816(acc[m][nt*2+0], ah[m], bhv[0], bhv[1]);
                mma16816(acc[m][nt*2+0], ah[m], blv[0], blv[1]);
                mma16816(acc[m][nt*2+0], al[m], bhv[0], bhv[1]);
                mma16816(acc[m][nt*2+1], ah[m], bhv[2], bhv[3]);
                mma16816(acc[m][nt*2+1], ah[m], blv[2], blv[3]);
                mma16816(acc[m][nt*2+1], al[m], bhv[2], bhv[3]);
            }
        }
    }

    float* Dsm = (float*)(smem_raw + D_OFF);
    #pragma unroll
    for (int m = 0; m < 2; m++) {
        const int r0 = mbase + m*16 + (l >> 2);
        #pragma unroll
        for (int nn = 0; nn < 4; nn++) {
            const int ncol = nbase + (nn >> 1)*16 + (nn & 1)*8 + 2*(l & 3);
            *(float2*)(Dsm + r0*DPITCH + ncol)     = make_float2(acc[m][nn][0], acc[m][nn][1]);
            *(float2*)(Dsm + (r0+8)*DPITCH + ncol) = make_float2(acc[m][nn][2], acc[m][nn][3]);
        }
    }
}

static __device__ __forceinline__ void epilogue_half(
    int half, int base, int wp, int l,
    const float* __restrict__ q, const float* __restrict__ w,
    const float* __restrict__ u, const float* __restrict__ a,
    float* __restrict__ dout, unsigned char* smem_raw)
{
    #pragma unroll
    for (int it = 0; it < 2; it++) {
        const int cc = wp*2 + it;
        const int c = cc + 32*half;
        const float* qc = q + base + c*(OO*DD);
        const float* wc = w + base + c*(OO*DD);
        const float* uc = u + base + c*(OO*DD);
        const float* ac = a + base + c*(OO*DD);

        float4 w0l = *(const float4*)(wc + l*4);
        float4 w1l = *(const float4*)(wc + DD + l*4);
        float4 q1l = *(const float4*)(qc + DD + l*4);
        float sw = fmaf(w1l.x, w0l.x, fmaf(w1l.y, w0l.y, fmaf(w1l.z, w0l.z, w1l.w*w0l.w)));
        float sq = fmaf(q1l.x, w0l.x, fmaf(q1l.y, w0l.y, fmaf(q1l.z, w0l.z, q1l.w*w0l.w)));
        #pragma unroll
        for (int o = 16; o; o >>= 1) {
            sw += __shfl_xor_sync(0xffffffffu, sw, o);
            sq += __shfl_xor_sync(0xffffffffu, sq, o);
        }

        const float* Dsm = (const float*)(smem_raw + D_OFF);
        float4 Aq0 = *(const float4*)(Dsm + ( 0 + cc)*DPITCH + 4*l);
        float4 Aw0 = *(const float4*)(Dsm + (32 + cc)*DPITCH + 4*l);
        float4 Aq1 = *(const float4*)(Dsm + (64 + cc)*DPITCH + 4*l);
        float4 Aw1 = *(const float4*)(Dsm + (96 + cc)*DPITCH + 4*l);

        float4 q0e = *(const float4*)(qc + l*4);
        float4 u0e = *(const float4*)(uc + l*4);
        float4 a0e = *(const float4*)(ac + l*4);
        float4 u1e = *(const float4*)(uc + DD + l*4);

        const float aq0[4] = {Aq0.x,Aq0.y,Aq0.z,Aq0.w}, aw0[4] = {Aw0.x,Aw0.y,Aw0.z,Aw0.w};
        const float aq1[4] = {Aq1.x,Aq1.y,Aq1.z,Aq1.w}, aw1[4] = {Aw1.x,Aw1.y,Aw1.z,Aw1.w};
        const float q0s[4] = {q0e.x,q0e.y,q0e.z,q0e.w}, u0s[4] = {u0e.x,u0e.y,u0e.z,u0e.w};
        const float a0s[4] = {a0e.x,a0e.y,a0e.z,a0e.w}, q1s[4] = {q1l.x,q1l.y,q1l.z,q1l.w};
        const float u1s[4] = {u1e.x,u1e.y,u1e.z,u1e.w};
        float o0[4], o1[4];
        #pragma unroll
        for (int e = 0; e < 4; e++) {
            float uv0  = u0s[e] - aw0[e];
            o0[e]      = fmaf(q0s[e], uv0, aq0[e]);
            float kth1 = fmaf(sw, uv0, a0s[e]*aw1[e]);
            float uv1  = u1s[e] - kth1;
            float oi1  = fmaf(sq, uv0, a0s[e]*aq1[e]);
            o1[e]      = fmaf(q1s[e], uv1, oi1);
        }
        *(float4*)(dout + base + c*(OO*DD) + l*4)      = make_float4(o0[0],o0[1],o0[2],o0[3]);
        *(float4*)(dout + base + c*(OO*DD) + DD + l*4) = make_float4(o1[0],o1[1],o1[2],o1[3]);
    }
}

// ---------------------------------------------------------------------------
// Consumer: pipelined. A0 staged BEFORE the flag wait; epilogue0 overlapped
// with A1 staging; 5 barriers per tile (incl. post-wait).
// ---------------------------------------------------------------------------
__device__ __forceinline__ void consume_tile(
    int tile, const float* __restrict__ q, const float* __restrict__ w,
    const float* __restrict__ u, const float* __restrict__ a,
    float* __restrict__ dout, unsigned char* smem_raw, uint32_t smem_base)
{
    const int t = threadIdx.x;
    const int base = tile * TILE_STRIDE;
    const int wp = t >> 5, l = t & 31;

    // Prefetch A half0 into smem during the (possible) wait window.
    stage_A_half(0, base, t, q, w, smem_raw);

    if (t == 0) {
        while (flag_acquire_ld(&g_sync[tile]) < 4) __nanosleep(64);
    }
    __syncthreads();                       // (1) flag visible to all

    stage_B(tile, t, smem_raw);
    __syncthreads();                       // (2) A0 + B staged

    gemm_half(wp, l, smem_base, smem_raw); // GEMM0 + Dsm0
    __syncthreads();                       // (3) Dsm0 ready; A free

    // Overlap: stage A1 (writes A region) with epilogue0 (reads Dsm + LDG)
    stage_A_half(1, base, t, q, w, smem_raw);
    epilogue_half(0, base, wp, l, q, w, u, a, dout, smem_raw);
    __syncthreads();                       // (4) A1 staged; epilogue0's Dsm reads done

    gemm_half(wp, l, smem_base, smem_raw); // GEMM1 + Dsm1
    __syncthreads();                       // (5) Dsm1 ready

    epilogue_half(1, base, wp, l, q, w, u, a, dout, smem_raw);
    // No trailing barrier: next tile's barrier (2) orders Dsm reads vs writes,
    // and next stage_A_half(0) only touches the A region (idle since GEMM1).
}

// ---------------------------------------------------------------------------

__global__ __launch_bounds__(NT, 1) __cluster_dims__(4, 1, 1) void fused_kernel(
    const float* __restrict__ q, const float* __restrict__ w,
    const float* __restrict__ u, const float* __restrict__ a,
    const float* __restrict__ init, const int* __restrict__ linflag,
    float* __restrict__ dout)
{
    extern __shared__ unsigned char smem_raw[];
    const uint32_t smem_base = smem_u32(smem_raw);
    const int t = threadIdx.x;
    const int b = blockIdx.x;

    if (b < NCHAINBLK)
        chain_role(b >> 2, b & 3, q, w, u, a, init, *linflag, dout,
                   (float*)smem_raw, smem_base);

    int* sjp = (int*)(smem_raw + CTRL_OFF);
    for (;;) {
        if (t == 0) *sjp = atomicAdd(&g_sync[NTILES], 1);
        __syncthreads();
        const int j = *sjp;
        __syncthreads();
        if (j >= NTILES) break;
        const int n = j >> 4, bh = j & 15;           // chunk-major = production order
        consume_tile(bh * NCC + n, q, w, u, a, dout, smem_raw, smem_base);
        __syncthreads();                              // epilogue1 done before ticket reuse of sjp
    }
}

extern "C" void kernel_launch(void* const* d_in, const int* in_sizes, int n_in,
                              void* d_out, int out_size) {
    const float* q    = (const float*)d_in[0];
    const float* w    = (const float*)d_in[1];
    const float* u    = (const float*)d_in[2];
    const float* a    = (const float*)d_in[3];
    const float* init = (const float*)d_in[4];
    const int*   lin  = (const int*)d_in[5];
    float* out = (float*)d_out;

    void* syncptr = nullptr;
    cudaGetSymbolAddress(&syncptr, g_sync);
    cudaMemsetAsync(syncptr, 0, (NTILES + 1) * sizeof(int));

    cudaFuncSetAttribute(fused_kernel, cudaFuncAttributeMaxDynamicSharedMemorySize, SMEM_BYTES);
    fused_kernel<<<GRID, NT, SMEM_BYTES>>>(q, w, u, a, init, lin, out);
}